// round 5
// baseline (speedup 1.0000x reference)
#include <cuda_runtime.h>
#include <math.h>

#define HW      65536
#define OUT_C   128
#define NCH     256   // 2*OUT_C
#define EPSBN   1e-5f
#define NSTATB  64    // stats blocks

// ---------------- per-channel constant pack (32 floats = 128B) ----------------
struct __align__(16) ChC {
    float g0x, g0y, g0c;   // alpha = g0x*x + g0y*y + g0c   (channel 2o)
    float g1x, g1y, g1c;   // beta
    float B[25];           // separable coeffs B[i][j], i=alpha basis, j=beta basis
    float pad;
};

__device__ ChC   g_chc[OUT_C];
__device__ float g_part[NSTATB * 5];

// exact trig tables: ang16[t] = t*22.5deg ; ang8[s] = s*45deg
__constant__ float COS16[16] = {
    1.f, 0.92387953251128674f, 0.70710678118654752f, 0.38268343236508977f,
    0.f,-0.38268343236508977f,-0.70710678118654752f,-0.92387953251128674f,
   -1.f,-0.92387953251128674f,-0.70710678118654752f,-0.38268343236508977f,
    0.f, 0.38268343236508977f, 0.70710678118654752f, 0.92387953251128674f };
__constant__ float SIN16[16] = {
    0.f, 0.38268343236508977f, 0.70710678118654752f, 0.92387953251128674f,
    1.f, 0.92387953251128674f, 0.70710678118654752f, 0.38268343236508977f,
    0.f,-0.38268343236508977f,-0.70710678118654752f,-0.92387953251128674f,
   -1.f,-0.92387953251128674f,-0.70710678118654752f,-0.38268343236508977f };
__constant__ float COS8[8] = { 1.f, 0.70710678118654752f, 0.f,-0.70710678118654752f,
                              -1.f,-0.70710678118654752f, 0.f, 0.70710678118654752f };
__constant__ float SIN8[8] = { 0.f, 0.70710678118654752f, 1.f, 0.70710678118654752f,
                               0.f,-0.70710678118654752f,-1.f,-0.70710678118654752f };

// ---------------- kernel 1: image moments (deterministic tree reduce) ----------
__global__ void stats_kernel(const float4* __restrict__ x4,
                             const float4* __restrict__ y4) {
    const int HW4 = HW / 4;
    float sx = 0.f, sy = 0.f, sxx = 0.f, syy = 0.f, sxy = 0.f;
    for (int p = blockIdx.x * blockDim.x + threadIdx.x; p < HW4;
         p += gridDim.x * blockDim.x) {
        float4 xv = __ldg(x4 + p), yv = __ldg(y4 + p);
        sx += xv.x + xv.y + xv.z + xv.w;
        sy += yv.x + yv.y + yv.z + yv.w;
        sxx = fmaf(xv.x, xv.x, fmaf(xv.y, xv.y, fmaf(xv.z, xv.z, fmaf(xv.w, xv.w, sxx))));
        syy = fmaf(yv.x, yv.x, fmaf(yv.y, yv.y, fmaf(yv.z, yv.z, fmaf(yv.w, yv.w, syy))));
        sxy = fmaf(xv.x, yv.x, fmaf(xv.y, yv.y, fmaf(xv.z, yv.z, fmaf(xv.w, yv.w, sxy))));
    }
    #pragma unroll
    for (int off = 16; off > 0; off >>= 1) {
        sx  += __shfl_down_sync(0xffffffffu, sx,  off);
        sy  += __shfl_down_sync(0xffffffffu, sy,  off);
        sxx += __shfl_down_sync(0xffffffffu, sxx, off);
        syy += __shfl_down_sync(0xffffffffu, syy, off);
        sxy += __shfl_down_sync(0xffffffffu, sxy, off);
    }
    __shared__ float sh[5][8];
    int w = threadIdx.x >> 5, l = threadIdx.x & 31;
    if (l == 0) { sh[0][w]=sx; sh[1][w]=sy; sh[2][w]=sxx; sh[3][w]=syy; sh[4][w]=sxy; }
    __syncthreads();
    if (threadIdx.x < 5) {
        float s = 0.f;
        #pragma unroll
        for (int i = 0; i < 8; ++i) s += sh[threadIdx.x][i];
        g_part[blockIdx.x * 5 + threadIdx.x] = s;
    }
}

// ---------------- kernel 2: BN fold (needs stats) -----------------------------
__global__ void bn_kernel(const float* __restrict__ freq,
                          const float* __restrict__ bnw,
                          const float* __restrict__ bnb) {
    __shared__ float stats[5];
    if (threadIdx.x < 5) {
        float s = 0.f;
        for (int i = 0; i < NSTATB; ++i) s += g_part[i*5 + threadIdx.x];
        stats[threadIdx.x] = s;
    }
    __syncthreads();
    int o = threadIdx.x;
    if (o >= OUT_C) return;
    const float N  = (float)HW;
    float mx  = stats[0] / N, my = stats[1] / N;
    float Sxx = stats[2] / N - mx * mx;
    float Syy = stats[3] / N - my * my;
    float Sxy = stats[4] / N - mx * my;
    float g[2][3];
    #pragma unroll
    for (int w = 0; w < 2; ++w) {
        int m = 2*o + w;
        float f0 = freq[m*2 + 0], f1 = freq[m*2 + 1];
        float mean = f0 * mx + f1 * my;
        float var  = f0*f0*Sxx + 2.f*f0*f1*Sxy + f1*f1*Syy;
        float s    = bnw[m] * rsqrtf(var + EPSBN);
        g[w][0] = f0 * s; g[w][1] = f1 * s; g[w][2] = bnb[m] - mean * s;
    }
    g_chc[o].g0x = g[0][0]; g_chc[o].g0y = g[0][1]; g_chc[o].g0c = g[0][2];
    g_chc[o].g1x = g[1][0]; g_chc[o].g1y = g[1][1]; g_chc[o].g1c = g[1][2];
}

// ---------------- kernel 3: circuit sampling + separable projection -----------
struct cpx { float r, i; };
__device__ __forceinline__ cpx cmul(cpx a, cpx b){ return {a.r*b.r - a.i*b.i, a.r*b.i + a.i*b.r}; }
__device__ __forceinline__ cpx cadd(cpx a, cpx b){ return {a.r + b.r, a.i + b.i}; }

// basis value f_i(2*pi*k/8): {1, cos, sin, cos2, sin2}
__device__ __forceinline__ float basisF(int i, int k) {
    switch (i) {
        case 0: return 1.f;
        case 1: return COS8[k];
        case 2: return SIN8[k];
        case 3: return COS8[(2*k) & 7];
        default: return SIN8[(2*k) & 7];
    }
}

// build layer s from shared U matrices
__device__ void build_layer_sh(const cpx (*sU)[2][2], int s, cpx A[4][4]) {
    for (int i = 0; i < 4; ++i)
        for (int j = 0; j < 4; ++j)
            A[i][j] = { (i == j) ? 1.f : 0.f, 0.f };
    for (int j = 0; j < 2; ++j) {
        for (int w = 0; w < 2; ++w) {
            const cpx (&U)[2][2] = sU[s*4 + j*2 + w];
            if (w == 0) { // wire 0: rows (q, 2+q)
                for (int q = 0; q < 2; ++q)
                    for (int c = 0; c < 4; ++c) {
                        cpx r0 = A[q][c], r1 = A[2+q][c];
                        A[q][c]   = cadd(cmul(U[0][0], r0), cmul(U[0][1], r1));
                        A[2+q][c] = cadd(cmul(U[1][0], r0), cmul(U[1][1], r1));
                    }
            } else {      // wire 1: rows (2q, 2q+1)
                for (int q = 0; q < 2; ++q)
                    for (int c = 0; c < 4; ++c) {
                        cpx r0 = A[2*q][c], r1 = A[2*q+1][c];
                        A[2*q][c]   = cadd(cmul(U[0][0], r0), cmul(U[0][1], r1));
                        A[2*q+1][c] = cadd(cmul(U[1][0], r0), cmul(U[1][1], r1));
                    }
            }
        }
        for (int c = 0; c < 4; ++c) { cpx t = A[2][c]; A[2][c] = A[3][c]; A[3][c] = t; }
    }
}

// one block per channel; 64 threads = 8x8 sample grid; threads 0..24 project
__global__ void circuit_kernel(const float* __restrict__ qp) {
    const int o = blockIdx.x;
    const int t = threadIdx.x;
    __shared__ cpx sU[12][2][2];
    __shared__ float sev[64];

    if (t < 12) {  // U3 matrix for (s = t>>2, j = (t>>1)&1, w = t&1)
        int s = t >> 2, j = (t >> 1) & 1, w = t & 1;
        const float* p = qp + (((s*2 + j) * NCH) + o*2 + w) * 3;
        float th = p[0], ph = p[1], lm = p[2];
        float st, ct; sincosf(0.5f * th, &st, &ct);
        float slm, clm; sincosf(lm, &slm, &clm);
        float sph, cph; sincosf(ph, &sph, &cph);
        float spl, cpl; sincosf(ph + lm, &spl, &cpl);
        sU[t][0][0] = { ct, 0.f };
        sU[t][0][1] = { -clm * st, -slm * st };
        sU[t][1][0] = {  cph * st,  sph * st };
        sU[t][1][1] = {  cpl * ct,  spl * ct };
    }
    __syncthreads();

    {
        cpx A0[4][4], A1[4][4], A2[4][4];
        build_layer_sh(sU, 0, A0);
        build_layer_sh(sU, 1, A1);
        build_layer_sh(sU, 2, A2);
        cpx v0[4];
        #pragma unroll
        for (int j = 0; j < 4; ++j) v0[j] = A0[j][0];

        int k = t >> 3, l = t & 7;           // alpha = 2pi k/8, beta = 2pi l/8
        int ia = (k + l) & 15;               // a = pi(k+l)/8
        int ib = (k - l) & 15;               // b = pi(k-l)/8
        cpx ema = { COS16[ia], -SIN16[ia] };
        cpx epa = { COS16[ia],  SIN16[ia] };
        cpx emb = { COS16[ib], -SIN16[ib] };
        cpx epb = { COS16[ib],  SIN16[ib] };

        cpx v[4];
        v[0] = cmul(ema, v0[0]); v[1] = cmul(emb, v0[1]);
        v[2] = cmul(epb, v0[2]); v[3] = cmul(epa, v0[3]);
        cpx u[4];
        #pragma unroll
        for (int j = 0; j < 4; ++j) {
            cpx acc = {0.f, 0.f};
            #pragma unroll
            for (int c = 0; c < 4; ++c) acc = cadd(acc, cmul(A1[j][c], v[c]));
            u[j] = acc;
        }
        cpx e[4];
        e[0] = cmul(ema, u[0]); e[1] = cmul(emb, u[1]);
        e[2] = cmul(epb, u[2]); e[3] = cmul(epa, u[3]);
        float ev = 0.f;
        #pragma unroll
        for (int j = 0; j < 4; ++j) {
            cpx acc = {0.f, 0.f};
            #pragma unroll
            for (int c = 0; c < 4; ++c) acc = cadd(acc, cmul(A2[j][c], e[c]));
            float m2 = acc.r * acc.r + acc.i * acc.i;
            ev += (j < 2) ? m2 : -m2;
        }
        sev[t] = ev;
    }
    __syncthreads();

    if (t < 25) {   // B[i][j] = norm * sum ev(k,l) * f_i(alpha_k) * f_j(beta_l)
        int i = t / 5, j = t % 5;
        float s = 0.f;
        for (int k = 0; k < 8; ++k) {
            float fi = basisF(i, k);
            float row = 0.f;
            for (int l = 0; l < 8; ++l)
                row = fmaf(sev[k * 8 + l], basisF(j, l), row);
            s = fmaf(fi, row, s);
        }
        float norm = (1.f / 64.f) * (i ? 2.f : 1.f) * (j ? 2.f : 1.f);
        g_chc[o].B[t] = s * norm;
    }
}

// ---------------- per-pixel evaluation (separable Fourier) --------------------
__device__ __forceinline__ float eval_point(const ChC& cc, float xv, float yv) {
    float al = fmaf(cc.g0x, xv, fmaf(cc.g0y, yv, cc.g0c));
    float be = fmaf(cc.g1x, xv, fmaf(cc.g1y, yv, cc.g1c));
    float s0, c0, s1, c1;
    __sincosf(al, &s0, &c0);
    __sincosf(be, &s1, &c1);
    float c2a = fmaf(2.f * c0, c0, -1.f), s2a = 2.f * s0 * c0;
    float c2b = fmaf(2.f * c1, c1, -1.f), s2b = 2.f * s1 * c1;

    const float* B = cc.B;
    float t0 = fmaf(B[1],  c1, fmaf(B[2],  s1, fmaf(B[3],  c2b, fmaf(B[4],  s2b, B[0]))));
    float t1 = fmaf(B[6],  c1, fmaf(B[7],  s1, fmaf(B[8],  c2b, fmaf(B[9],  s2b, B[5]))));
    float t2 = fmaf(B[11], c1, fmaf(B[12], s1, fmaf(B[13], c2b, fmaf(B[14], s2b, B[10]))));
    float t3 = fmaf(B[16], c1, fmaf(B[17], s1, fmaf(B[18], c2b, fmaf(B[19], s2b, B[15]))));
    float t4 = fmaf(B[21], c1, fmaf(B[22], s1, fmaf(B[23], c2b, fmaf(B[24], s2b, B[20]))));
    return fmaf(t1, c0, fmaf(t2, s0, fmaf(t3, c2a, fmaf(t4, s2a, t0))));
}

// ---------------- kernel 4: main ----------------------------------------------
__global__ void __launch_bounds__(256)
main_kernel(const float4* __restrict__ x4, const float4* __restrict__ y4,
            float4* __restrict__ out4) {
    const int o = blockIdx.y;
    const ChC cc = g_chc[o];             // by-value -> registers
    const int HW4 = HW / 4;
    float4* __restrict__ o0 = out4 + (size_t)o * HW4;

    for (int g = blockIdx.x * blockDim.x + threadIdx.x; g < HW4;
         g += gridDim.x * blockDim.x) {
        float4 xv = __ldg(x4 + g);
        float4 yv = __ldg(y4 + g);
        float4 r;
        r.x = eval_point(cc, xv.x, yv.x);
        r.y = eval_point(cc, xv.y, yv.y);
        r.z = eval_point(cc, xv.z, yv.z);
        r.w = eval_point(cc, xv.w, yv.w);
        o0[g]                           = r;
        o0[g + (size_t)1 * OUT_C * HW4] = r;
        o0[g + (size_t)2 * OUT_C * HW4] = r;
        o0[g + (size_t)3 * OUT_C * HW4] = r;
    }
}

// ---------------- launch ------------------------------------------------------
extern "C" void kernel_launch(void* const* d_in, const int* in_sizes, int n_in,
                              void* d_out, int out_size) {
    const float* coords = (const float*)d_in[0];   // (4, 2, 256, 256)
    const float* freq   = (const float*)d_in[1];   // (256, 2)
    const float* qp     = (const float*)d_in[2];   // (1, 3, 2, 256, 3)
    const float* bnw    = (const float*)d_in[3];   // (256,)
    const float* bnb    = (const float*)d_in[4];   // (256,)

    stats_kernel<<<NSTATB, 256>>>((const float4*)coords,
                                  (const float4*)(coords + HW));
    circuit_kernel<<<OUT_C, 64>>>(qp);
    bn_kernel<<<1, 128>>>(freq, bnw, bnb);

    dim3 grid(16, OUT_C);
    main_kernel<<<grid, 256>>>((const float4*)coords,
                               (const float4*)(coords + HW),
                               (float4*)d_out);
}

// round 6
// speedup vs baseline: 1.0996x; 1.0996x over previous
#include <cuda_runtime.h>
#include <math.h>

#define HW      65536
#define OUT_C   128
#define NCH     256   // 2*OUT_C
#define EPSBN   1e-5f
#define NSTATB  64    // stats blocks

// ---------------- per-channel circuit coefficients ----------------------------
struct __align__(16) ChB {
    float B[25];           // separable coeffs B[i][j], i=alpha basis, j=beta basis
    float pad[7];
};

__device__ ChB   g_chb[OUT_C];
__device__ float g_part[5 * NSTATB];   // [stat][block]

// exact trig tables: ang16[t] = t*22.5deg ; ang8[s] = s*45deg
__constant__ float COS16[16] = {
    1.f, 0.92387953251128674f, 0.70710678118654752f, 0.38268343236508977f,
    0.f,-0.38268343236508977f,-0.70710678118654752f,-0.92387953251128674f,
   -1.f,-0.92387953251128674f,-0.70710678118654752f,-0.38268343236508977f,
    0.f, 0.38268343236508977f, 0.70710678118654752f, 0.92387953251128674f };
__constant__ float SIN16[16] = {
    0.f, 0.38268343236508977f, 0.70710678118654752f, 0.92387953251128674f,
    1.f, 0.92387953251128674f, 0.70710678118654752f, 0.38268343236508977f,
    0.f,-0.38268343236508977f,-0.70710678118654752f,-0.92387953251128674f,
   -1.f,-0.92387953251128674f,-0.70710678118654752f,-0.38268343236508977f };
__constant__ float COS8[8] = { 1.f, 0.70710678118654752f, 0.f,-0.70710678118654752f,
                              -1.f,-0.70710678118654752f, 0.f, 0.70710678118654752f };
__constant__ float SIN8[8] = { 0.f, 0.70710678118654752f, 1.f, 0.70710678118654752f,
                               0.f,-0.70710678118654752f,-1.f,-0.70710678118654752f };

// ---------------- circuit helpers ---------------------------------------------
struct cpx { float r, i; };
__device__ __forceinline__ cpx cmul(cpx a, cpx b){ return {a.r*b.r - a.i*b.i, a.r*b.i + a.i*b.r}; }
__device__ __forceinline__ cpx cadd(cpx a, cpx b){ return {a.r + b.r, a.i + b.i}; }

__device__ __forceinline__ float basisF(int i, int k) {
    switch (i) {
        case 0: return 1.f;
        case 1: return COS8[k];
        case 2: return SIN8[k];
        case 3: return COS8[(2*k) & 7];
        default: return SIN8[(2*k) & 7];
    }
}

__device__ void build_layer_sh(const cpx (*sU)[2][2], int s, cpx A[4][4]) {
    for (int i = 0; i < 4; ++i)
        for (int j = 0; j < 4; ++j)
            A[i][j] = { (i == j) ? 1.f : 0.f, 0.f };
    for (int j = 0; j < 2; ++j) {
        for (int w = 0; w < 2; ++w) {
            const cpx (&U)[2][2] = sU[s*4 + j*2 + w];
            if (w == 0) {
                for (int q = 0; q < 2; ++q)
                    for (int c = 0; c < 4; ++c) {
                        cpx r0 = A[q][c], r1 = A[2+q][c];
                        A[q][c]   = cadd(cmul(U[0][0], r0), cmul(U[0][1], r1));
                        A[2+q][c] = cadd(cmul(U[1][0], r0), cmul(U[1][1], r1));
                    }
            } else {
                for (int q = 0; q < 2; ++q)
                    for (int c = 0; c < 4; ++c) {
                        cpx r0 = A[2*q][c], r1 = A[2*q+1][c];
                        A[2*q][c]   = cadd(cmul(U[0][0], r0), cmul(U[0][1], r1));
                        A[2*q+1][c] = cadd(cmul(U[1][0], r0), cmul(U[1][1], r1));
                    }
            }
        }
        for (int c = 0; c < 4; ++c) { cpx t = A[2][c]; A[2][c] = A[3][c]; A[3][c] = t; }
    }
}

// ---------------- kernel 1: fused stats (blocks 0..63) + circuit (64..191) ----
__global__ void __launch_bounds__(256)
prep_kernel(const float4* __restrict__ x4, const float4* __restrict__ y4,
            const float* __restrict__ qp) {
    const int t = threadIdx.x;

    if (blockIdx.x < NSTATB) {
        // ----- stats: exactly one float4 pair per thread -----
        int p = blockIdx.x * 256 + t;          // p < 16384 = HW/4
        float4 xv = __ldg(x4 + p), yv = __ldg(y4 + p);
        float sx  = xv.x + xv.y + xv.z + xv.w;
        float sy  = yv.x + yv.y + yv.z + yv.w;
        float sxx = fmaf(xv.x, xv.x, fmaf(xv.y, xv.y, fmaf(xv.z, xv.z, xv.w * xv.w)));
        float syy = fmaf(yv.x, yv.x, fmaf(yv.y, yv.y, fmaf(yv.z, yv.z, yv.w * yv.w)));
        float sxy = fmaf(xv.x, yv.x, fmaf(xv.y, yv.y, fmaf(xv.z, yv.z, xv.w * yv.w)));
        #pragma unroll
        for (int off = 16; off > 0; off >>= 1) {
            sx  += __shfl_down_sync(0xffffffffu, sx,  off);
            sy  += __shfl_down_sync(0xffffffffu, sy,  off);
            sxx += __shfl_down_sync(0xffffffffu, sxx, off);
            syy += __shfl_down_sync(0xffffffffu, syy, off);
            sxy += __shfl_down_sync(0xffffffffu, sxy, off);
        }
        __shared__ float sh[5][8];
        int w = t >> 5, l = t & 31;
        if (l == 0) { sh[0][w]=sx; sh[1][w]=sy; sh[2][w]=sxx; sh[3][w]=syy; sh[4][w]=sxy; }
        __syncthreads();
        if (t < 5) {
            float s = 0.f;
            #pragma unroll
            for (int i = 0; i < 8; ++i) s += sh[t][i];
            g_part[t * NSTATB + blockIdx.x] = s;
        }
        return;
    }

    // ----- circuit: one block per channel -----
    const int o = blockIdx.x - NSTATB;
    __shared__ cpx sU[12][2][2];
    __shared__ float sev[64];

    if (t < 12) {  // U3 matrix for (s = t>>2, j = (t>>1)&1, w = t&1)
        int s = t >> 2, j = (t >> 1) & 1, w = t & 1;
        const float* p = qp + (((s*2 + j) * NCH) + o*2 + w) * 3;
        float th = p[0], ph = p[1], lm = p[2];
        float st, ct; sincosf(0.5f * th, &st, &ct);
        float slm, clm; sincosf(lm, &slm, &clm);
        float sph, cph; sincosf(ph, &sph, &cph);
        float spl, cpl; sincosf(ph + lm, &spl, &cpl);
        sU[t][0][0] = { ct, 0.f };
        sU[t][0][1] = { -clm * st, -slm * st };
        sU[t][1][0] = {  cph * st,  sph * st };
        sU[t][1][1] = {  cpl * ct,  spl * ct };
    }
    __syncthreads();

    if (t < 64) {
        cpx A0[4][4], A1[4][4], A2[4][4];
        build_layer_sh(sU, 0, A0);
        build_layer_sh(sU, 1, A1);
        build_layer_sh(sU, 2, A2);
        cpx v0[4];
        #pragma unroll
        for (int j = 0; j < 4; ++j) v0[j] = A0[j][0];

        int k = t >> 3, l = t & 7;           // alpha = 2pi k/8, beta = 2pi l/8
        int ia = (k + l) & 15;               // a = pi(k+l)/8
        int ib = (k - l) & 15;               // b = pi(k-l)/8
        cpx ema = { COS16[ia], -SIN16[ia] };
        cpx epa = { COS16[ia],  SIN16[ia] };
        cpx emb = { COS16[ib], -SIN16[ib] };
        cpx epb = { COS16[ib],  SIN16[ib] };

        cpx v[4];
        v[0] = cmul(ema, v0[0]); v[1] = cmul(emb, v0[1]);
        v[2] = cmul(epb, v0[2]); v[3] = cmul(epa, v0[3]);
        cpx u[4];
        #pragma unroll
        for (int j = 0; j < 4; ++j) {
            cpx acc = {0.f, 0.f};
            #pragma unroll
            for (int c = 0; c < 4; ++c) acc = cadd(acc, cmul(A1[j][c], v[c]));
            u[j] = acc;
        }
        cpx e[4];
        e[0] = cmul(ema, u[0]); e[1] = cmul(emb, u[1]);
        e[2] = cmul(epb, u[2]); e[3] = cmul(epa, u[3]);
        float ev = 0.f;
        #pragma unroll
        for (int j = 0; j < 4; ++j) {
            cpx acc = {0.f, 0.f};
            #pragma unroll
            for (int c = 0; c < 4; ++c) acc = cadd(acc, cmul(A2[j][c], e[c]));
            float m2 = acc.r * acc.r + acc.i * acc.i;
            ev += (j < 2) ? m2 : -m2;
        }
        sev[t] = ev;
    }
    __syncthreads();

    if (t < 25) {   // B[i][j] = norm * sum ev(k,l) * f_i(alpha_k) * f_j(beta_l)
        int i = t / 5, j = t % 5;
        float s = 0.f;
        for (int k = 0; k < 8; ++k) {
            float fi = basisF(i, k);
            float row = 0.f;
            for (int l = 0; l < 8; ++l)
                row = fmaf(sev[k * 8 + l], basisF(j, l), row);
            s = fmaf(fi, row, s);
        }
        float norm = (1.f / 64.f) * (i ? 2.f : 1.f) * (j ? 2.f : 1.f);
        g_chb[o].B[t] = s * norm;
    }
}

// ---------------- per-pixel evaluation (separable Fourier) --------------------
__device__ __forceinline__ float eval_point(const float* __restrict__ B,
                                            const float* __restrict__ g,
                                            float xv, float yv) {
    float al = fmaf(g[0], xv, fmaf(g[1], yv, g[2]));
    float be = fmaf(g[3], xv, fmaf(g[4], yv, g[5]));
    float s0, c0, s1, c1;
    __sincosf(al, &s0, &c0);
    __sincosf(be, &s1, &c1);
    float c2a = fmaf(2.f * c0, c0, -1.f), s2a = 2.f * s0 * c0;
    float c2b = fmaf(2.f * c1, c1, -1.f), s2b = 2.f * s1 * c1;

    float t0 = fmaf(B[1],  c1, fmaf(B[2],  s1, fmaf(B[3],  c2b, fmaf(B[4],  s2b, B[0]))));
    float t1 = fmaf(B[6],  c1, fmaf(B[7],  s1, fmaf(B[8],  c2b, fmaf(B[9],  s2b, B[5]))));
    float t2 = fmaf(B[11], c1, fmaf(B[12], s1, fmaf(B[13], c2b, fmaf(B[14], s2b, B[10]))));
    float t3 = fmaf(B[16], c1, fmaf(B[17], s1, fmaf(B[18], c2b, fmaf(B[19], s2b, B[15]))));
    float t4 = fmaf(B[21], c1, fmaf(B[22], s1, fmaf(B[23], c2b, fmaf(B[24], s2b, B[20]))));
    return fmaf(t1, c0, fmaf(t2, s0, fmaf(t3, c2a, fmaf(t4, s2a, t0))));
}

// ---------------- kernel 2: main (inline BN fold prologue) --------------------
__global__ void __launch_bounds__(256)
main_kernel(const float4* __restrict__ x4, const float4* __restrict__ y4,
            const float* __restrict__ freq, const float* __restrict__ bnw,
            const float* __restrict__ bnb, float4* __restrict__ out4) {
    const int o = blockIdx.y;
    const int tid = threadIdx.x, w = tid >> 5, l = tid & 31;

    __shared__ float sstats[5];
    __shared__ float sg[6];

    // deterministic fixed-order reduction of the 5x64 stats partials
    if (w < 5) {
        float v = g_part[w * NSTATB + l] + g_part[w * NSTATB + 32 + l];
        #pragma unroll
        for (int off = 16; off > 0; off >>= 1)
            v += __shfl_down_sync(0xffffffffu, v, off);
        if (l == 0) sstats[w] = v;
    }
    __syncthreads();
    if (tid == 0) {
        const float N  = (float)HW;
        float mx  = sstats[0] / N, my = sstats[1] / N;
        float Sxx = sstats[2] / N - mx * mx;
        float Syy = sstats[3] / N - my * my;
        float Sxy = sstats[4] / N - mx * my;
        #pragma unroll
        for (int s = 0; s < 2; ++s) {
            int m = 2*o + s;
            float f0 = freq[m*2 + 0], f1 = freq[m*2 + 1];
            float mean = f0 * mx + f1 * my;
            float var  = f0*f0*Sxx + 2.f*f0*f1*Sxy + f1*f1*Syy;
            float sc   = bnw[m] * rsqrtf(var + EPSBN);
            sg[3*s + 0] = f0 * sc;
            sg[3*s + 1] = f1 * sc;
            sg[3*s + 2] = bnb[m] - mean * sc;
        }
    }
    __syncthreads();

    float g[6];
    #pragma unroll
    for (int i = 0; i < 6; ++i) g[i] = sg[i];
    float B[25];
    #pragma unroll
    for (int i = 0; i < 25; ++i) B[i] = g_chb[o].B[i];

    const int HW4 = HW / 4;
    float4* __restrict__ o0 = out4 + (size_t)o * HW4;

    for (int p = blockIdx.x * blockDim.x + tid; p < HW4;
         p += gridDim.x * blockDim.x) {
        float4 xv = __ldg(x4 + p);
        float4 yv = __ldg(y4 + p);
        float4 r;
        r.x = eval_point(B, g, xv.x, yv.x);
        r.y = eval_point(B, g, xv.y, yv.y);
        r.z = eval_point(B, g, xv.z, yv.z);
        r.w = eval_point(B, g, xv.w, yv.w);
        __stcs(&o0[p],                           r);
        __stcs(&o0[p + (size_t)1 * OUT_C * HW4], r);
        __stcs(&o0[p + (size_t)2 * OUT_C * HW4], r);
        __stcs(&o0[p + (size_t)3 * OUT_C * HW4], r);
    }
}

// ---------------- launch ------------------------------------------------------
extern "C" void kernel_launch(void* const* d_in, const int* in_sizes, int n_in,
                              void* d_out, int out_size) {
    const float* coords = (const float*)d_in[0];   // (4, 2, 256, 256)
    const float* freq   = (const float*)d_in[1];   // (256, 2)
    const float* qp     = (const float*)d_in[2];   // (1, 3, 2, 256, 3)
    const float* bnw    = (const float*)d_in[3];   // (256,)
    const float* bnb    = (const float*)d_in[4];   // (256,)

    const float4* x4 = (const float4*)coords;
    const float4* y4 = (const float4*)(coords + HW);

    prep_kernel<<<NSTATB + OUT_C, 256>>>(x4, y4, qp);

    dim3 grid(16, OUT_C);
    main_kernel<<<grid, 256>>>(x4, y4, freq, bnw, bnb, (float4*)d_out);
}